// round 15
// baseline (speedup 1.0000x reference)
#include <cuda_runtime.h>
#include <cuda_fp16.h>
#include <math.h>
#include <stdint.h>

#define NTOT 32768
#define DIM  128
#define KC   4096
#define CHW  131072

#define OFF_LOSS 4194304
#define OFF_PERP 4194305
#define OFF_ENC  4194306
#define OFF_IDX  138412034

#define GAP_THRESH 2.5e-3f

// ---------------- device scratch ----------------
__device__ __align__(16) __half g_Bph[KC * 128];  // w_hi only, scaled x64 (1MB)
__device__ __align__(16) float g_wsq[KC];
__device__ int   g_idx[NTOT];
__device__ int   g_counts[KC];
__device__ float g_partials[1024];
__device__ int   g_flag[NTOT];
__device__ int   g_nflag;

// ---------------- PTX helpers ----------------
__device__ __forceinline__ uint32_t smem_u32(const void* p) {
    uint32_t a;
    asm("{ .reg .u64 t; cvta.to.shared.u64 t, %1; cvt.u32.u64 %0, t; }" : "=r"(a) : "l"(p));
    return a;
}
__device__ __forceinline__ void cp_async16(uint32_t dst, const void* src) {
    asm volatile("cp.async.cg.shared.global [%0], [%1], 16;" :: "r"(dst), "l"(src) : "memory");
}
#define CP_COMMIT() asm volatile("cp.async.commit_group;" ::: "memory")
#define CP_WAIT0()  asm volatile("cp.async.wait_group 0;" ::: "memory")

#define LDSM4(R, addr) \
    asm volatile("ldmatrix.sync.aligned.m8n8.x4.shared.b16 {%0,%1,%2,%3}, [%4];" \
        : "=r"((R)[0]), "=r"((R)[1]), "=r"((R)[2]), "=r"((R)[3]) : "r"(addr))

#define MMA16816(C, A, b0, b1) \
    asm volatile("mma.sync.aligned.m16n8k16.row.col.f32.f16.f16.f32 " \
        "{%0,%1,%2,%3}, {%4,%5,%6,%7}, {%8,%9}, {%0,%1,%2,%3};" \
        : "+f"((C)[0]), "+f"((C)[1]), "+f"((C)[2]), "+f"((C)[3]) \
        : "r"((A)[0]), "r"((A)[1]), "r"((A)[2]), "r"((A)[3]), "r"(b0), "r"(b1))

// ---------------- fused prep: W -> fp16 hi (scaled), wsq, zero counts/nflag ----------------
__global__ void prep_kernel(const float* __restrict__ w) {
    const int blk = blockIdx.x;                 // 512 blocks
    const int warp = threadIdx.x >> 5, lane = threadIdx.x & 31;
    const int k = blk * 8 + warp;
    float4 v = ((const float4*)w)[k * 32 + lane];
    __half2* dst = (__half2*)g_Bph + k * 64 + lane * 2;
    dst[0] = __floats2half2_rn(v.x * 64.0f, v.y * 64.0f);
    dst[1] = __floats2half2_rn(v.z * 64.0f, v.w * 64.0f);
    float s = v.x * v.x + v.y * v.y + v.z * v.z + v.w * v.w;
    #pragma unroll
    for (int o = 16; o; o >>= 1) s += __shfl_down_sync(0xffffffffu, s, o);
    if (lane == 0) g_wsq[k] = s;
    if (blk < 16) g_counts[blk * 256 + threadIdx.x] = 0;
    if (blk == 0 && threadIdx.x == 0) g_nflag = 0;
}

// ---------------- fp16 mma.sync distance GEMM + fused top-2 argmin + enc zero-fill ----------------
// CTA: 256 threads (2x4 warp grid, warp tile 64x32), 2 CTAs/SM.
// A: x_hi, 128 rows x 128 halves (pitch 272B). B: ring-2, stage = 128 codes x 128 halves.
// 32 stages; per stage: LDSM/MMA first, THEN fill stores (off the critical LSU path),
// then epilogue (wsq via one float2 __ldg per nt).
// xsq: per-thread register accumulation; no smem atomics (R14-proven).
#define A_PITCH_H 136
#define B_STG   34816
#define SM_A    0
#define SM_B    34816
#define SM_XSQ  104448
#define SM_XSP  104960
#define SM_RV   105984
#define SM_RI   108032
#define SM_R2   110080
#define SMEM_TOTAL 112128

__global__ void __launch_bounds__(256, 2) argmin_mma_kernel(const float* __restrict__ x,
                                                            float* __restrict__ enc) {
    extern __shared__ char sm[];
    __half* Asm   = (__half*)(sm + SM_A);
    float*  xsq_s = (float*)(sm + SM_XSQ);
    float*  xsq_p = (float*)(sm + SM_XSP);   // 256 partials
    float*  rv    = (float*)(sm + SM_RV);
    int*    ri    = (int*)(sm + SM_RI);
    float*  r2    = (float*)(sm + SM_R2);
    const uint32_t smb = smem_u32(sm);

    const int tid   = threadIdx.x;
    const int lane  = tid & 31;
    const int warp  = tid >> 5;
    const int warpM = warp >> 2;      // 0..1
    const int warpN = warp & 3;       // 0..3
    const int n0 = blockIdx.x << 7;
    const int b  = n0 >> 10;
    const int nb = n0 & 1023;

    // this CTA's 2MB encodings slice (rows n0..n0+127).
    // slice base = enc + n0*4096 floats; byte addr ≡ 8 (mod 16) -> +2 floats is 16B-aligned.
    float* encp = enc + (size_t)n0 * KC;
    float4* enc4 = (float4*)(encp + 2);          // 131071 float4 cover floats [2, 524286)
    const float4 zero4 = make_float4(0.f, 0.f, 0.f, 0.f);
    if (tid == 0) {                              // head + tail float2
        encp[0] = 0.f; encp[1] = 0.f;
        encp[524286] = 0.f; encp[524287] = 0.f;
    }

    // cp.async issue: stage s = code chunk s (128 codes x 128 halves), ring slot s&1
    const int crow = tid >> 1;        // 0..127
    const int chalf = tid & 1;
    auto issue = [&](int st) {
        const char* src = (const char*)g_Bph + ((size_t)(st * 128 + crow)) * 256 + chalf * 128;
        uint32_t dst = smb + SM_B + (st & 1) * B_STG + crow * 272 + chalf * 128;
        #pragma unroll
        for (int i = 0; i < 8; i++) cp_async16(dst + i * 16, src + (size_t)i * 16);
    };

    issue(0); CP_COMMIT();

    // build A: x_hi; xsq accumulated in a register (row r = tid & 127 is fixed per thread)
    {
        const int r = tid & 127;
        const int d0 = tid >> 7;                 // 0 or 1
        const float* xr = x + (size_t)b * CHW + nb + r;
        float accq = 0.f;
        #pragma unroll 4
        for (int it = 0; it < 64; it++) {
            int d = d0 + it * 2;
            float v = __ldg(xr + (size_t)d * 1024);
            Asm[r * A_PITCH_H + d] = __float2half_rn(v);
            accq = fmaf(v, v, accq);
        }
        xsq_p[tid] = accq;
    }
    __syncthreads();
    if (tid < 128) xsq_s[tid] = xsq_p[tid] + xsq_p[tid + 128] + 1e-8f;
    __syncthreads();

    const uint32_t a_base = smb + SM_A +
        (uint32_t)((warpM * 64 + (lane & 15)) * 272 + ((lane >> 4) * 16));
    const uint32_t b_base = smb + SM_B +
        (uint32_t)((warpN * 32 + (lane & 7) + ((lane & 16) ? 8 : 0)) * 272 + ((lane & 8) ? 16 : 0));

    float acc[4][4][4];
    #pragma unroll
    for (int mt = 0; mt < 4; mt++)
        #pragma unroll
        for (int nt = 0; nt < 4; nt++)
            #pragma unroll
            for (int q = 0; q < 4; q++) acc[mt][nt][q] = 0.f;

    float bval[8]; int bidx[8]; float b2v[8];
    #pragma unroll
    for (int m = 0; m < 8; m++) { bval[m] = 3.4e38f; bidx[m] = 0; b2v[m] = 3.4e38f; }

    for (int s = 0; s < 32; s++) {
        CP_WAIT0();
        __syncthreads();
        if (s + 1 < 32) { issue(s + 1); CP_COMMIT(); }

        const uint32_t bbase = b_base + (uint32_t)((s & 1) * B_STG);

        #pragma unroll
        for (int j = 0; j < 8; j++) {
            uint32_t ak = a_base + j * 32;
            uint32_t bk = bbase + j * 32;
            uint32_t A0[4], A1[4], A2[4], A3[4], B0[4], B1[4];
            LDSM4(A0, ak);
            LDSM4(A1, ak + 16 * 272);
            LDSM4(A2, ak + 32 * 272);
            LDSM4(A3, ak + 48 * 272);
            LDSM4(B0, bk);
            LDSM4(B1, bk + 16 * 272);

            MMA16816(acc[0][0], A0, B0[0], B0[1]);
            MMA16816(acc[0][1], A0, B0[2], B0[3]);
            MMA16816(acc[0][2], A0, B1[0], B1[1]);
            MMA16816(acc[0][3], A0, B1[2], B1[3]);
            MMA16816(acc[1][0], A1, B0[0], B0[1]);
            MMA16816(acc[1][1], A1, B0[2], B0[3]);
            MMA16816(acc[1][2], A1, B1[0], B1[1]);
            MMA16816(acc[1][3], A1, B1[2], B1[3]);
            MMA16816(acc[2][0], A2, B0[0], B0[1]);
            MMA16816(acc[2][1], A2, B0[2], B0[3]);
            MMA16816(acc[2][2], A2, B1[0], B1[1]);
            MMA16816(acc[2][3], A2, B1[2], B1[3]);
            MMA16816(acc[3][0], A3, B0[0], B0[1]);
            MMA16816(acc[3][1], A3, B0[2], B0[3]);
            MMA16816(acc[3][2], A3, B1[0], B1[1]);
            MMA16816(acc[3][3], A3, B1[2], B1[3]);
        }

        // fill AFTER the MMA chain: stores overlap epilogue math instead of delaying LDSM
        {
            int base = s * 4096 + tid;
            #pragma unroll
            for (int i = 0; i < 16; i++) {
                int idx = base + i * 256;
                if (idx < 131071) __stcs(&enc4[idx], zero4);
            }
        }

        // epilogue: acc = 64 * x_hi.w_hi over full D. dist = xsq - acc/32 + wsq (float2 __ldg).
        {
            const int cb = s * 128 + warpN * 32 + (lane & 3) * 2;
            #pragma unroll
            for (int mt = 0; mt < 4; mt++) {
                int r0 = warpM * 64 + mt * 16 + (lane >> 2);
                float xq0 = xsq_s[r0];
                float xq1 = xsq_s[r0 + 8];
                int m0 = mt * 2, m1 = mt * 2 + 1;
                #pragma unroll
                for (int nt = 0; nt < 4; nt++) {
                    int c0 = cb + nt * 8;
                    float2 ww = __ldg((const float2*)&g_wsq[c0]);
                    float* a4 = acc[mt][nt];
                    float d00 = fmaf(a4[0], -0.03125f, xq0) + ww.x;
                    float d01 = fmaf(a4[1], -0.03125f, xq0) + ww.y;
                    float d10 = fmaf(a4[2], -0.03125f, xq1) + ww.x;
                    float d11 = fmaf(a4[3], -0.03125f, xq1) + ww.y;
                    if (d00 < bval[m0]) { b2v[m0] = bval[m0]; bval[m0] = d00; bidx[m0] = c0; }
                    else if (d00 < b2v[m0]) b2v[m0] = d00;
                    if (d01 < bval[m0]) { b2v[m0] = bval[m0]; bval[m0] = d01; bidx[m0] = c0 + 1; }
                    else if (d01 < b2v[m0]) b2v[m0] = d01;
                    if (d10 < bval[m1]) { b2v[m1] = bval[m1]; bval[m1] = d10; bidx[m1] = c0; }
                    else if (d10 < b2v[m1]) b2v[m1] = d10;
                    if (d11 < bval[m1]) { b2v[m1] = bval[m1]; bval[m1] = d11; bidx[m1] = c0 + 1; }
                    else if (d11 < b2v[m1]) b2v[m1] = d11;
                    a4[0] = 0.f; a4[1] = 0.f; a4[2] = 0.f; a4[3] = 0.f;
                }
            }
        }
    }

    // top-2 merge across the 4 lanes sharing each row
    #pragma unroll
    for (int m = 0; m < 8; m++) {
        #pragma unroll
        for (int off = 1; off < 4; off <<= 1) {
            float ov = __shfl_xor_sync(0xffffffffu, bval[m], off);
            int   oi = __shfl_xor_sync(0xffffffffu, bidx[m], off);
            float os = __shfl_xor_sync(0xffffffffu, b2v[m], off);
            if (ov < bval[m] || (ov == bval[m] && oi < bidx[m])) {
                b2v[m] = fminf(bval[m], os);
                bval[m] = ov; bidx[m] = oi;
            } else {
                b2v[m] = fminf(b2v[m], ov);
            }
        }
    }
    if ((lane & 3) == 0) {
        #pragma unroll
        for (int mt = 0; mt < 4; mt++) {
            int r0 = warpM * 64 + mt * 16 + (lane >> 2);
            rv[warpN * 128 + r0]     = bval[mt * 2];
            ri[warpN * 128 + r0]     = bidx[mt * 2];
            r2[warpN * 128 + r0]     = b2v[mt * 2];
            rv[warpN * 128 + r0 + 8] = bval[mt * 2 + 1];
            ri[warpN * 128 + r0 + 8] = bidx[mt * 2 + 1];
            r2[warpN * 128 + r0 + 8] = b2v[mt * 2 + 1];
        }
    }
    __syncthreads();
    if (tid < 128) {
        float bv = rv[tid]; int bi = ri[tid]; float s2 = r2[tid];
        #pragma unroll
        for (int q = 1; q < 4; q++) {
            float v = rv[q * 128 + tid]; int ii = ri[q * 128 + tid]; float os = r2[q * 128 + tid];
            if (v < bv || (v == bv && ii < bi)) { s2 = fminf(bv, os); bv = v; bi = ii; }
            else                                { s2 = fminf(s2, v); }
        }
        g_idx[n0 + tid] = bi;
        if (s2 - bv < GAP_THRESH) {
            int p = atomicAdd(&g_nflag, 1);
            g_flag[p] = n0 + tid;
        }
    }
}

// ---------------- rescue: exact fp32 re-argmin for near-tie rows ----------------
__global__ void __launch_bounds__(256, 1) rescue_kernel(const float* __restrict__ x,
                                                        const float* __restrict__ w) {
    __shared__ __align__(16) float xs[4][128];
    __shared__ float xsq_sh[4];
    __shared__ float redv[256];
    __shared__ int   redi[256];
    const int tid = threadIdx.x;
    const int nf = g_nflag;

    for (int base = blockIdx.x * 4; base < nf; base += gridDim.x * 4) {
        const int cnt = min(4, nf - base);
        __syncthreads();
        if (tid < 128) {
            for (int r = 0; r < cnt; r++) {
                int row = g_flag[base + r];
                int bb = row >> 10, nb = row & 1023;
                xs[r][tid] = x[(size_t)bb * CHW + (size_t)tid * 1024 + nb];
            }
        }
        __syncthreads();
        if (tid < 4) {
            float s = 0.f;
            if (tid < cnt)
                for (int d = 0; d < 128; d++) s = fmaf(xs[tid][d], xs[tid][d], s);
            xsq_sh[tid] = s + 1e-8f;
        }
        __syncthreads();

        float bv[4]; int bi[4];
        #pragma unroll
        for (int r = 0; r < 4; r++) { bv[r] = 3.4e38f; bi[r] = 0; }

        const float4* w4 = (const float4*)w;
        for (int g = 0; g < 4; g++) {
            const int k0 = g * 1024 + tid * 4;
            float dacc[4][4];
            #pragma unroll
            for (int r = 0; r < 4; r++)
                #pragma unroll
                for (int j = 0; j < 4; j++) dacc[r][j] = 0.f;
            #pragma unroll 4
            for (int d4 = 0; d4 < 32; d4++) {
                float4 xv[4];
                #pragma unroll
                for (int r = 0; r < 4; r++) xv[r] = ((const float4*)xs[r])[d4];
                #pragma unroll
                for (int j = 0; j < 4; j++) {
                    float4 wv = w4[(size_t)(k0 + j) * 32 + d4];
                    #pragma unroll
                    for (int r = 0; r < 4; r++) {
                        float t = dacc[r][j];
                        t = fmaf(xv[r].x, wv.x, t);
                        t = fmaf(xv[r].y, wv.y, t);
                        t = fmaf(xv[r].z, wv.z, t);
                        t = fmaf(xv[r].w, wv.w, t);
                        dacc[r][j] = t;
                    }
                }
            }
            #pragma unroll
            for (int j = 0; j < 4; j++) {
                int k = k0 + j;
                float wq = g_wsq[k];
                #pragma unroll
                for (int r = 0; r < 4; r++) {
                    float dist = fmaf(-2.f, dacc[r][j], xsq_sh[r]) + wq;
                    if (dist < bv[r]) { bv[r] = dist; bi[r] = k; }
                }
            }
        }

        for (int r = 0; r < cnt; r++) {
            redv[tid] = bv[r]; redi[tid] = bi[r];
            __syncthreads();
            for (int o = 128; o; o >>= 1) {
                if (tid < o) {
                    float v = redv[tid + o]; int ii = redi[tid + o];
                    if (v < redv[tid] || (v == redv[tid] && ii < redi[tid])) { redv[tid] = v; redi[tid] = ii; }
                }
                __syncthreads();
            }
            if (tid == 0) g_idx[g_flag[base + r]] = redi[0];
            __syncthreads();
        }
    }
}

// ---------------- gather quantized + loss partials + counts/idx/enc scatter ----------------
__global__ void gather_kernel(const float* __restrict__ x, const float* __restrict__ wgt,
                              float* __restrict__ outq, float* __restrict__ out_idx,
                              float* __restrict__ enc) {
    __shared__ int idx_s[32];
    __shared__ float red[256];
    const int blk = blockIdx.x;
    const int b = blk >> 5, h = blk & 31;
    const int n0 = blk * 32;
    const int tid = threadIdx.x;
    if (tid < 32) idx_s[tid] = g_idx[n0 + tid];
    __syncthreads();

    // per-n side outputs (post-rescue indices)
    if (tid < 32) {
        int id = idx_s[tid];
        atomicAdd(&g_counts[id], 1);
        out_idx[n0 + tid] = (float)id;
        enc[(size_t)(n0 + tid) * KC + id] = 1.0f;
    }

    const int w = tid & 31, dg = tid >> 5;
    const size_t bse = (size_t)b * CHW + h * 32 + w;
    float sum = 0.f;
    #pragma unroll
    for (int j = 0; j < 16; j++) {
        int d = dg + (j << 3);
        size_t lin = bse + (size_t)d * 1024;
        float q = wgt[idx_s[w] * DIM + d];
        float xv = x[lin];
        outq[lin] = q;
        float df = q - xv;
        sum = fmaf(df, df, sum);
    }
    red[tid] = sum;
    __syncthreads();
    #pragma unroll
    for (int o = 128; o; o >>= 1) { if (tid < o) red[tid] += red[tid + o]; __syncthreads(); }
    if (tid == 0) g_partials[blk] = red[0];
}

__global__ void finalize_kernel(float* __restrict__ out_loss, float* __restrict__ out_perp) {
    __shared__ float red[256];
    const int tid = threadIdx.x;

    float s = 0.f;
    for (int i = tid; i < 1024; i += 256) s += g_partials[i];
    red[tid] = s;
    __syncthreads();
    #pragma unroll
    for (int o = 128; o; o >>= 1) { if (tid < o) red[tid] += red[tid + o]; __syncthreads(); }
    if (tid == 0) {
        float mse = red[0] * (1.0f / 4194304.0f);
        float loss = mse * 1.25f;
        if (isnan(loss) || isinf(loss)) loss = 0.1f;
        *out_loss = loss;
    }
    __syncthreads();

    float hsum = 0.f;
    for (int i = tid; i < KC; i += 256) {
        float p = (float)g_counts[i] * (1.0f / (float)NTOT);
        hsum += p * logf(p + 1e-10f);
    }
    red[tid] = hsum;
    __syncthreads();
    #pragma unroll
    for (int o = 128; o; o >>= 1) { if (tid < o) red[tid] += red[tid + o]; __syncthreads(); }
    if (tid == 0) *out_perp = expf(-red[0]);
}

// ---------------- launch ----------------
extern "C" void kernel_launch(void* const* d_in, const int* in_sizes, int n_in,
                              void* d_out, int out_size) {
    const float* x;
    const float* w;
    if (in_sizes[0] == KC * DIM) { w = (const float*)d_in[0]; x = (const float*)d_in[1]; }
    else                         { x = (const float*)d_in[0]; w = (const float*)d_in[1]; }

    float* out = (float*)d_out;
    float* out_q    = out;
    float* out_loss = out + OFF_LOSS;
    float* out_perp = out + OFF_PERP;
    float* out_enc  = out + OFF_ENC;
    float* out_idx  = out + OFF_IDX;

    cudaFuncSetAttribute(argmin_mma_kernel, cudaFuncAttributeMaxDynamicSharedMemorySize, SMEM_TOTAL);

    prep_kernel<<<512, 256>>>(w);
    argmin_mma_kernel<<<256, 256, SMEM_TOTAL>>>(x, out_enc);
    rescue_kernel<<<256, 256>>>(x, w);
    gather_kernel<<<1024, 256>>>(x, w, out_q, out_idx, out_enc);
    finalize_kernel<<<1, 256>>>(out_loss, out_perp);
}

// round 16
// speedup vs baseline: 1.1426x; 1.1426x over previous
#include <cuda_runtime.h>
#include <cuda_fp16.h>
#include <math.h>
#include <stdint.h>

#define NTOT 32768
#define DIM  128
#define KC   4096
#define CHW  131072

#define OFF_LOSS 4194304
#define OFF_PERP 4194305
#define OFF_ENC  4194306
#define OFF_IDX  138412034

#define GAP_THRESH 2.5e-3f

// ---------------- device scratch ----------------
__device__ __align__(16) __half g_Bph[KC * 128];  // w_hi only, scaled x64 (1MB)
__device__ __align__(16) float g_wsq[KC];
__device__ int   g_idx[NTOT];
__device__ int   g_counts[KC];
__device__ float g_partials[1024];
__device__ int   g_flag[NTOT];
__device__ int   g_nflag;
__device__ int   g_done;

// ---------------- PTX helpers ----------------
__device__ __forceinline__ uint32_t smem_u32(const void* p) {
    uint32_t a;
    asm("{ .reg .u64 t; cvta.to.shared.u64 t, %1; cvt.u32.u64 %0, t; }" : "=r"(a) : "l"(p));
    return a;
}
__device__ __forceinline__ void cp_async16(uint32_t dst, const void* src) {
    asm volatile("cp.async.cg.shared.global [%0], [%1], 16;" :: "r"(dst), "l"(src) : "memory");
}
#define CP_COMMIT() asm volatile("cp.async.commit_group;" ::: "memory")
#define CP_WAIT0()  asm volatile("cp.async.wait_group 0;" ::: "memory")

#define LDSM4(R, addr) \
    asm volatile("ldmatrix.sync.aligned.m8n8.x4.shared.b16 {%0,%1,%2,%3}, [%4];" \
        : "=r"((R)[0]), "=r"((R)[1]), "=r"((R)[2]), "=r"((R)[3]) : "r"(addr))

#define MMA16816(C, A, b0, b1) \
    asm volatile("mma.sync.aligned.m16n8k16.row.col.f32.f16.f16.f32 " \
        "{%0,%1,%2,%3}, {%4,%5,%6,%7}, {%8,%9}, {%0,%1,%2,%3};" \
        : "+f"((C)[0]), "+f"((C)[1]), "+f"((C)[2]), "+f"((C)[3]) \
        : "r"((A)[0]), "r"((A)[1]), "r"((A)[2]), "r"((A)[3]), "r"(b0), "r"(b1))

// ---------------- fused prep: W -> fp16 hi (scaled), wsq, zero counts/nflag/done ----------------
__global__ void prep_kernel(const float* __restrict__ w) {
    const int blk = blockIdx.x;                 // 512 blocks
    const int warp = threadIdx.x >> 5, lane = threadIdx.x & 31;
    const int k = blk * 8 + warp;
    float4 v = ((const float4*)w)[k * 32 + lane];
    __half2* dst = (__half2*)g_Bph + k * 64 + lane * 2;
    dst[0] = __floats2half2_rn(v.x * 64.0f, v.y * 64.0f);
    dst[1] = __floats2half2_rn(v.z * 64.0f, v.w * 64.0f);
    float s = v.x * v.x + v.y * v.y + v.z * v.z + v.w * v.w;
    #pragma unroll
    for (int o = 16; o; o >>= 1) s += __shfl_down_sync(0xffffffffu, s, o);
    if (lane == 0) g_wsq[k] = s;
    if (blk < 16) g_counts[blk * 256 + threadIdx.x] = 0;
    if (blk == 0 && threadIdx.x == 0) { g_nflag = 0; g_done = 0; }
}

// ---------------- fp16 mma.sync distance GEMM + fused top-2 argmin + enc zero-fill ----------------
// R14-proven mainloop: 2 CTAs/SM, ring-2, fill BEFORE the MMA chain, scalar wsq __ldg,
// register-accumulated xsq prologue (no smem atomics).
#define A_PITCH_H 136
#define B_STG   34816
#define SM_A    0
#define SM_B    34816
#define SM_XSQ  104448
#define SM_XSP  104960
#define SM_RV   105984
#define SM_RI   108032
#define SM_R2   110080
#define SMEM_TOTAL 112128

__global__ void __launch_bounds__(256, 2) argmin_mma_kernel(const float* __restrict__ x,
                                                            float* __restrict__ enc) {
    extern __shared__ char sm[];
    __half* Asm   = (__half*)(sm + SM_A);
    float*  xsq_s = (float*)(sm + SM_XSQ);
    float*  xsq_p = (float*)(sm + SM_XSP);   // 256 partials
    float*  rv    = (float*)(sm + SM_RV);
    int*    ri    = (int*)(sm + SM_RI);
    float*  r2    = (float*)(sm + SM_R2);
    const uint32_t smb = smem_u32(sm);

    const int tid   = threadIdx.x;
    const int lane  = tid & 31;
    const int warp  = tid >> 5;
    const int warpM = warp >> 2;      // 0..1
    const int warpN = warp & 3;       // 0..3
    const int n0 = blockIdx.x << 7;
    const int b  = n0 >> 10;
    const int nb = n0 & 1023;

    // this CTA's 2MB encodings slice (rows n0..n0+127).
    // slice base = enc + n0*4096 floats; byte addr ≡ 8 (mod 16) -> +2 floats is 16B-aligned.
    float* encp = enc + (size_t)n0 * KC;
    float4* enc4 = (float4*)(encp + 2);          // 131071 float4 cover floats [2, 524286)
    const float4 zero4 = make_float4(0.f, 0.f, 0.f, 0.f);
    if (tid == 0) {                              // head + tail float2
        encp[0] = 0.f; encp[1] = 0.f;
        encp[524286] = 0.f; encp[524287] = 0.f;
    }

    // cp.async issue: stage s = code chunk s (128 codes x 128 halves), ring slot s&1
    const int crow = tid >> 1;        // 0..127
    const int chalf = tid & 1;
    auto issue = [&](int st) {
        const char* src = (const char*)g_Bph + ((size_t)(st * 128 + crow)) * 256 + chalf * 128;
        uint32_t dst = smb + SM_B + (st & 1) * B_STG + crow * 272 + chalf * 128;
        #pragma unroll
        for (int i = 0; i < 8; i++) cp_async16(dst + i * 16, src + (size_t)i * 16);
    };

    issue(0); CP_COMMIT();

    // build A: x_hi; xsq accumulated in a register (row r = tid & 127 is fixed per thread)
    {
        const int r = tid & 127;
        const int d0 = tid >> 7;                 // 0 or 1
        const float* xr = x + (size_t)b * CHW + nb + r;
        float accq = 0.f;
        #pragma unroll 4
        for (int it = 0; it < 64; it++) {
            int d = d0 + it * 2;
            float v = __ldg(xr + (size_t)d * 1024);
            Asm[r * A_PITCH_H + d] = __float2half_rn(v);
            accq = fmaf(v, v, accq);
        }
        xsq_p[tid] = accq;
    }
    __syncthreads();
    if (tid < 128) xsq_s[tid] = xsq_p[tid] + xsq_p[tid + 128] + 1e-8f;
    __syncthreads();

    const uint32_t a_base = smb + SM_A +
        (uint32_t)((warpM * 64 + (lane & 15)) * 272 + ((lane >> 4) * 16));
    const uint32_t b_base = smb + SM_B +
        (uint32_t)((warpN * 32 + (lane & 7) + ((lane & 16) ? 8 : 0)) * 272 + ((lane & 8) ? 16 : 0));

    float acc[4][4][4];
    #pragma unroll
    for (int mt = 0; mt < 4; mt++)
        #pragma unroll
        for (int nt = 0; nt < 4; nt++)
            #pragma unroll
            for (int q = 0; q < 4; q++) acc[mt][nt][q] = 0.f;

    float bval[8]; int bidx[8]; float b2v[8];
    #pragma unroll
    for (int m = 0; m < 8; m++) { bval[m] = 3.4e38f; bidx[m] = 0; b2v[m] = 3.4e38f; }

    for (int s = 0; s < 32; s++) {
        CP_WAIT0();
        __syncthreads();
        if (s + 1 < 32) { issue(s + 1); CP_COMMIT(); }

        // stream 16 coalesced float4 zeros with .cs hint (64KB/stage/CTA);
        // last slot of stage 31 is out of range
        {
            int base = s * 4096 + tid;
            #pragma unroll
            for (int i = 0; i < 16; i++) {
                int idx = base + i * 256;
                if (idx < 131071) __stcs(&enc4[idx], zero4);
            }
        }

        const uint32_t bbase = b_base + (uint32_t)((s & 1) * B_STG);

        #pragma unroll
        for (int j = 0; j < 8; j++) {
            uint32_t ak = a_base + j * 32;
            uint32_t bk = bbase + j * 32;
            uint32_t A0[4], A1[4], A2[4], A3[4], B0[4], B1[4];
            LDSM4(A0, ak);
            LDSM4(A1, ak + 16 * 272);
            LDSM4(A2, ak + 32 * 272);
            LDSM4(A3, ak + 48 * 272);
            LDSM4(B0, bk);
            LDSM4(B1, bk + 16 * 272);

            MMA16816(acc[0][0], A0, B0[0], B0[1]);
            MMA16816(acc[0][1], A0, B0[2], B0[3]);
            MMA16816(acc[0][2], A0, B1[0], B1[1]);
            MMA16816(acc[0][3], A0, B1[2], B1[3]);
            MMA16816(acc[1][0], A1, B0[0], B0[1]);
            MMA16816(acc[1][1], A1, B0[2], B0[3]);
            MMA16816(acc[1][2], A1, B1[0], B1[1]);
            MMA16816(acc[1][3], A1, B1[2], B1[3]);
            MMA16816(acc[2][0], A2, B0[0], B0[1]);
            MMA16816(acc[2][1], A2, B0[2], B0[3]);
            MMA16816(acc[2][2], A2, B1[0], B1[1]);
            MMA16816(acc[2][3], A2, B1[2], B1[3]);
            MMA16816(acc[3][0], A3, B0[0], B0[1]);
            MMA16816(acc[3][1], A3, B0[2], B0[3]);
            MMA16816(acc[3][2], A3, B1[0], B1[1]);
            MMA16816(acc[3][3], A3, B1[2], B1[3]);
        }

        // epilogue: acc = 64 * x_hi.w_hi over full D. dist = xsq - acc/32 + wsq (wsq via __ldg).
        {
            const int cb = s * 128 + warpN * 32 + (lane & 3) * 2;
            #pragma unroll
            for (int mt = 0; mt < 4; mt++) {
                int r0 = warpM * 64 + mt * 16 + (lane >> 2);
                float xq0 = xsq_s[r0];
                float xq1 = xsq_s[r0 + 8];
                int m0 = mt * 2, m1 = mt * 2 + 1;
                #pragma unroll
                for (int nt = 0; nt < 4; nt++) {
                    int c0 = cb + nt * 8;
                    float w0 = __ldg(&g_wsq[c0]);
                    float w1 = __ldg(&g_wsq[c0 + 1]);
                    float* a4 = acc[mt][nt];
                    float d00 = fmaf(a4[0], -0.03125f, xq0) + w0;
                    float d01 = fmaf(a4[1], -0.03125f, xq0) + w1;
                    float d10 = fmaf(a4[2], -0.03125f, xq1) + w0;
                    float d11 = fmaf(a4[3], -0.03125f, xq1) + w1;
                    if (d00 < bval[m0]) { b2v[m0] = bval[m0]; bval[m0] = d00; bidx[m0] = c0; }
                    else if (d00 < b2v[m0]) b2v[m0] = d00;
                    if (d01 < bval[m0]) { b2v[m0] = bval[m0]; bval[m0] = d01; bidx[m0] = c0 + 1; }
                    else if (d01 < b2v[m0]) b2v[m0] = d01;
                    if (d10 < bval[m1]) { b2v[m1] = bval[m1]; bval[m1] = d10; bidx[m1] = c0; }
                    else if (d10 < b2v[m1]) b2v[m1] = d10;
                    if (d11 < bval[m1]) { b2v[m1] = bval[m1]; bval[m1] = d11; bidx[m1] = c0 + 1; }
                    else if (d11 < b2v[m1]) b2v[m1] = d11;
                    a4[0] = 0.f; a4[1] = 0.f; a4[2] = 0.f; a4[3] = 0.f;
                }
            }
        }
    }

    // top-2 merge across the 4 lanes sharing each row
    #pragma unroll
    for (int m = 0; m < 8; m++) {
        #pragma unroll
        for (int off = 1; off < 4; off <<= 1) {
            float ov = __shfl_xor_sync(0xffffffffu, bval[m], off);
            int   oi = __shfl_xor_sync(0xffffffffu, bidx[m], off);
            float os = __shfl_xor_sync(0xffffffffu, b2v[m], off);
            if (ov < bval[m] || (ov == bval[m] && oi < bidx[m])) {
                b2v[m] = fminf(bval[m], os);
                bval[m] = ov; bidx[m] = oi;
            } else {
                b2v[m] = fminf(b2v[m], ov);
            }
        }
    }
    if ((lane & 3) == 0) {
        #pragma unroll
        for (int mt = 0; mt < 4; mt++) {
            int r0 = warpM * 64 + mt * 16 + (lane >> 2);
            rv[warpN * 128 + r0]     = bval[mt * 2];
            ri[warpN * 128 + r0]     = bidx[mt * 2];
            r2[warpN * 128 + r0]     = b2v[mt * 2];
            rv[warpN * 128 + r0 + 8] = bval[mt * 2 + 1];
            ri[warpN * 128 + r0 + 8] = bidx[mt * 2 + 1];
            r2[warpN * 128 + r0 + 8] = b2v[mt * 2 + 1];
        }
    }
    __syncthreads();
    if (tid < 128) {
        float bv = rv[tid]; int bi = ri[tid]; float s2 = r2[tid];
        #pragma unroll
        for (int q = 1; q < 4; q++) {
            float v = rv[q * 128 + tid]; int ii = ri[q * 128 + tid]; float os = r2[q * 128 + tid];
            if (v < bv || (v == bv && ii < bi)) { s2 = fminf(bv, os); bv = v; bi = ii; }
            else                                { s2 = fminf(s2, v); }
        }
        g_idx[n0 + tid] = bi;
        if (s2 - bv < GAP_THRESH) {
            int p = atomicAdd(&g_nflag, 1);
            g_flag[p] = n0 + tid;
        }
    }
}

// ---------------- rescue: exact fp32 re-argmin for near-tie rows ----------------
__global__ void __launch_bounds__(256, 1) rescue_kernel(const float* __restrict__ x,
                                                        const float* __restrict__ w) {
    __shared__ __align__(16) float xs[4][128];
    __shared__ float xsq_sh[4];
    __shared__ float redv[256];
    __shared__ int   redi[256];
    const int tid = threadIdx.x;
    const int nf = g_nflag;

    for (int base = blockIdx.x * 4; base < nf; base += gridDim.x * 4) {
        const int cnt = min(4, nf - base);
        __syncthreads();
        if (tid < 128) {
            for (int r = 0; r < cnt; r++) {
                int row = g_flag[base + r];
                int bb = row >> 10, nb = row & 1023;
                xs[r][tid] = x[(size_t)bb * CHW + (size_t)tid * 1024 + nb];
            }
        }
        __syncthreads();
        if (tid < 4) {
            float s = 0.f;
            if (tid < cnt)
                for (int d = 0; d < 128; d++) s = fmaf(xs[tid][d], xs[tid][d], s);
            xsq_sh[tid] = s + 1e-8f;
        }
        __syncthreads();

        float bv[4]; int bi[4];
        #pragma unroll
        for (int r = 0; r < 4; r++) { bv[r] = 3.4e38f; bi[r] = 0; }

        const float4* w4 = (const float4*)w;
        for (int g = 0; g < 4; g++) {
            const int k0 = g * 1024 + tid * 4;
            float dacc[4][4];
            #pragma unroll
            for (int r = 0; r < 4; r++)
                #pragma unroll
                for (int j = 0; j < 4; j++) dacc[r][j] = 0.f;
            #pragma unroll 4
            for (int d4 = 0; d4 < 32; d4++) {
                float4 xv[4];
                #pragma unroll
                for (int r = 0; r < 4; r++) xv[r] = ((const float4*)xs[r])[d4];
                #pragma unroll
                for (int j = 0; j < 4; j++) {
                    float4 wv = w4[(size_t)(k0 + j) * 32 + d4];
                    #pragma unroll
                    for (int r = 0; r < 4; r++) {
                        float t = dacc[r][j];
                        t = fmaf(xv[r].x, wv.x, t);
                        t = fmaf(xv[r].y, wv.y, t);
                        t = fmaf(xv[r].z, wv.z, t);
                        t = fmaf(xv[r].w, wv.w, t);
                        dacc[r][j] = t;
                    }
                }
            }
            #pragma unroll
            for (int j = 0; j < 4; j++) {
                int k = k0 + j;
                float wq = g_wsq[k];
                #pragma unroll
                for (int r = 0; r < 4; r++) {
                    float dist = fmaf(-2.f, dacc[r][j], xsq_sh[r]) + wq;
                    if (dist < bv[r]) { bv[r] = dist; bi[r] = k; }
                }
            }
        }

        for (int r = 0; r < cnt; r++) {
            redv[tid] = bv[r]; redi[tid] = bi[r];
            __syncthreads();
            for (int o = 128; o; o >>= 1) {
                if (tid < o) {
                    float v = redv[tid + o]; int ii = redi[tid + o];
                    if (v < redv[tid] || (v == redv[tid] && ii < redi[tid])) { redv[tid] = v; redi[tid] = ii; }
                }
                __syncthreads();
            }
            if (tid == 0) g_idx[g_flag[base + r]] = redi[0];
            __syncthreads();
        }
    }
}

// ---------------- gather + loss partials + counts/idx/enc scatter + last-block finalize ----------------
__global__ void gather_kernel(const float* __restrict__ x, const float* __restrict__ wgt,
                              float* __restrict__ outq, float* __restrict__ out_idx,
                              float* __restrict__ enc,
                              float* __restrict__ out_loss, float* __restrict__ out_perp) {
    __shared__ int idx_s[32];
    __shared__ float red[256];
    __shared__ bool is_last;
    const int blk = blockIdx.x;
    const int b = blk >> 5, h = blk & 31;
    const int n0 = blk * 32;
    const int tid = threadIdx.x;
    if (tid < 32) idx_s[tid] = g_idx[n0 + tid];
    __syncthreads();

    // per-n side outputs (post-rescue indices)
    if (tid < 32) {
        int id = idx_s[tid];
        atomicAdd(&g_counts[id], 1);
        out_idx[n0 + tid] = (float)id;
        enc[(size_t)(n0 + tid) * KC + id] = 1.0f;
    }

    const int w = tid & 31, dg = tid >> 5;
    const size_t bse = (size_t)b * CHW + h * 32 + w;
    float sum = 0.f;
    #pragma unroll
    for (int j = 0; j < 16; j++) {
        int d = dg + (j << 3);
        size_t lin = bse + (size_t)d * 1024;
        float q = wgt[idx_s[w] * DIM + d];
        float xv = x[lin];
        outq[lin] = q;
        float df = q - xv;
        sum = fmaf(df, df, sum);
    }
    red[tid] = sum;
    __syncthreads();
    #pragma unroll
    for (int o = 128; o; o >>= 1) { if (tid < o) red[tid] += red[tid + o]; __syncthreads(); }
    if (tid == 0) g_partials[blk] = red[0];

    // last-block finalize: loss + perplexity
    __threadfence();
    if (tid == 0) is_last = (atomicAdd(&g_done, 1) == 1023);
    __syncthreads();
    if (!is_last) return;

    float s = 0.f;
    for (int i = tid; i < 1024; i += 256) s += g_partials[i];
    red[tid] = s;
    __syncthreads();
    #pragma unroll
    for (int o = 128; o; o >>= 1) { if (tid < o) red[tid] += red[tid + o]; __syncthreads(); }
    if (tid == 0) {
        float mse = red[0] * (1.0f / 4194304.0f);
        float loss = mse * 1.25f;
        if (isnan(loss) || isinf(loss)) loss = 0.1f;
        *out_loss = loss;
    }
    __syncthreads();

    float hsum = 0.f;
    for (int i = tid; i < KC; i += 256) {
        float p = (float)g_counts[i] * (1.0f / (float)NTOT);
        hsum += p * logf(p + 1e-10f);
    }
    red[tid] = hsum;
    __syncthreads();
    #pragma unroll
    for (int o = 128; o; o >>= 1) { if (tid < o) red[tid] += red[tid + o]; __syncthreads(); }
    if (tid == 0) *out_perp = expf(-red[0]);
}

// ---------------- launch ----------------
extern "C" void kernel_launch(void* const* d_in, const int* in_sizes, int n_in,
                              void* d_out, int out_size) {
    const float* x;
    const float* w;
    if (in_sizes[0] == KC * DIM) { w = (const float*)d_in[0]; x = (const float*)d_in[1]; }
    else                         { x = (const float*)d_in[0]; w = (const float*)d_in[1]; }

    float* out = (float*)d_out;
    float* out_q    = out;
    float* out_loss = out + OFF_LOSS;
    float* out_perp = out + OFF_PERP;
    float* out_enc  = out + OFF_ENC;
    float* out_idx  = out + OFF_IDX;

    cudaFuncSetAttribute(argmin_mma_kernel, cudaFuncAttributeMaxDynamicSharedMemorySize, SMEM_TOTAL);

    prep_kernel<<<512, 256>>>(w);
    argmin_mma_kernel<<<256, 256, SMEM_TOTAL>>>(x, out_enc);
    rescue_kernel<<<256, 256>>>(x, w);
    gather_kernel<<<1024, 256>>>(x, w, out_q, out_idx, out_enc, out_loss, out_perp);
}